// round 11
// baseline (speedup 1.0000x reference)
#include <cuda_runtime.h>
#include <cuda_fp16.h>
#include <math.h>
#include <stdint.h>

#define S_TOT 2560
#define TXT 256
#define IMG 2304
#define D 3072
#define NH 24
#define DH 128
#define ND3 9216
#define KDIM 3072
#define ATT_SCALE 0.08838834764831845f   // 1/sqrt(128)
#define CEXP (1.4426950408889634f * ATT_SCALE)
#define EPS 1e-5f

// ---------------- scratch (device globals: no allocation allowed) ----------------
__device__ __half g_qkvh[(size_t)S_TOT * ND3];
__device__ __half g_qfh[(size_t)NH * S_TOT * DH];   // fragment-packed fp16
__device__ __half g_kfh[(size_t)NH * S_TOT * DH];
__device__ __half g_vfh[(size_t)NH * S_TOT * DH];
__device__ __half g_attnh[(size_t)S_TOT * D];
// fp16 copies of inputs
__device__ __half g_xh[(size_t)S_TOT * D];
__device__ __half g_wqkvh[(size_t)ND3 * D];
__device__ __half g_waddqkvh[(size_t)ND3 * D];
__device__ __half g_wouth[(size_t)D * D];
__device__ __half g_waddouth[(size_t)D * D];

// ================= helpers =================
static __device__ __forceinline__ uint32_t smem_u32(const void* p) {
    uint32_t r;
    asm("{ .reg .u64 t; cvta.to.shared.u64 t, %1; cvt.u32.u64 %0, t; }" : "=r"(r) : "l"(p));
    return r;
}
static __device__ __forceinline__ void cp16(uint32_t dst, const void* src) {
    asm volatile("cp.async.cg.shared.global [%0], [%1], 16;" :: "r"(dst), "l"(src));
}
#define CP_COMMIT() asm volatile("cp.async.commit_group;" ::: "memory")
#define CP_WAIT(n)  asm volatile("cp.async.wait_group %0;" :: "n"(n) : "memory")

static __device__ __forceinline__ void mma_f16(
    float& c0, float& c1, float& c2, float& c3,
    uint32_t a0, uint32_t a1, uint32_t a2, uint32_t a3,
    uint32_t b0, uint32_t b1)
{
    asm volatile(
        "mma.sync.aligned.m16n8k16.row.col.f32.f16.f16.f32 "
        "{%0,%1,%2,%3}, {%4,%5,%6,%7}, {%8,%9}, {%0,%1,%2,%3};"
        : "+f"(c0), "+f"(c1), "+f"(c2), "+f"(c3)
        : "r"(a0), "r"(a1), "r"(a2), "r"(a3), "r"(b0), "r"(b1));
}
static __device__ __forceinline__ void ldsm_x4(
    uint32_t& r0, uint32_t& r1, uint32_t& r2, uint32_t& r3, uint32_t addr)
{
    asm volatile("ldmatrix.sync.aligned.m8n8.x4.shared.b16 {%0,%1,%2,%3}, [%4];"
                 : "=r"(r0), "=r"(r1), "=r"(r2), "=r"(r3) : "r"(addr));
}
static __device__ __forceinline__ uint32_t pack_h2(float x, float y) {
    __half2 h = __float22half2_rn(make_float2(x, y));
    return *reinterpret_cast<uint32_t*>(&h);
}
static __device__ __forceinline__ float ex2f(float x) {
    float r;
    asm("ex2.approx.f32 %0, %1;" : "=f"(r) : "f"(x));
    return r;
}

// ---------------- single merged fp32 -> fp16 conversion pass ----------------
__global__ void conv_all(const float4* __restrict__ enc, const float4* __restrict__ hid,
                         const float4* __restrict__ wq,  const float4* __restrict__ waq,
                         const float4* __restrict__ wo,  const float4* __restrict__ wao,
                         __half2* __restrict__ xh,
                         __half2* __restrict__ wqh, __half2* __restrict__ waqh,
                         __half2* __restrict__ woh, __half2* __restrict__ waoh)
{
    const int NE = TXT * D / 4, NHd = IMG * D / 4;
    const int NW = ND3 * D / 4, NO = D * D / 4;
    const int TOT = NE + NHd + 2 * NW + 2 * NO;
    int i = blockIdx.x * blockDim.x + threadIdx.x;
    if (i >= TOT) return;

    const float4* s; __half2* d; int k;
    if (i < NE)                        { s = enc; d = xh;                      k = i; }
    else if (i < NE + NHd)             { s = hid; d = xh + (size_t)NE * 2;     k = i - NE; }
    else if (i < NE + NHd + NW)        { s = wq;  d = wqh;                     k = i - NE - NHd; }
    else if (i < NE + NHd + 2 * NW)    { s = waq; d = waqh;                    k = i - NE - NHd - NW; }
    else if (i < NE + NHd + 2 * NW + NO){ s = wo; d = woh;                     k = i - NE - NHd - 2 * NW; }
    else                               { s = wao; d = waoh;                    k = i - NE - NHd - 2 * NW - NO; }

    float4 v = s[k];
    d[k * 2]     = __float22half2_rn(make_float2(v.x, v.y));
    d[k * 2 + 1] = __float22half2_rn(make_float2(v.z, v.w));
}

// ================= fp16 mma.sync GEMM (unchanged) =================
#define BM 128
#define BN 128
#define BK 64
#define GSTG 3
#define NCHUNK (KDIM / BK)       // 48
#define HPITCH 72
#define A_SH (BM * HPITCH)
#define B_SH (BN * HPITCH)
#define GEMM_SMEM_BYTES (GSTG * (A_SH + B_SH) * 2)   // 110592

template <typename OT>
__global__ __launch_bounds__(128, 2)
void gemm_f16(const __half* __restrict__ A,
              const __half* __restrict__ W0, const __half* __restrict__ W1,
              const float* __restrict__ b0, const float* __restrict__ b1,
              OT* __restrict__ C0, OT* __restrict__ C1,
              int M0, int N)
{
    extern __shared__ __half hsm[];
    __half* Asm = hsm;
    __half* Bsm = hsm + GSTG * A_SH;

    const int tid  = threadIdx.x;
    const int lane = tid & 31;
    const int wid  = tid >> 5;
    const int wm   = wid >> 1;
    const int wn   = wid & 1;
    const int g    = lane >> 2;
    const int t    = lane & 3;

    const int bm = blockIdx.x, bn = blockIdx.y;
    const int rowbase = bm * BM;
    const int n0 = bn * BN;

    const __half* Ab = A + (size_t)rowbase * KDIM;
    const __half* W; const float* bias; OT* C;
    if (rowbase < M0) { W = W0; bias = b0; C = C0 + (size_t)rowbase * N; }
    else              { W = W1; bias = b1; C = C1 + (size_t)(rowbase - M0) * N; }

    const uint32_t asu = smem_u32(Asm);
    const uint32_t bsu = smem_u32(Bsm);

    const uint32_t aL = asu + (uint32_t)(((wm * 64 + (lane & 15)) * HPITCH
                                          + (lane >> 4) * 8) * 2);
    const uint32_t bL = bsu + (uint32_t)(((wn * 64 + (lane & 7) + (lane >> 4) * 8) * HPITCH
                                          + ((lane >> 3) & 1) * 8) * 2);

    auto load_chunk = [&](int ck, int st) {
        const int k0 = ck * BK;
        const uint32_t au = asu + st * (A_SH * 2);
        const uint32_t bu = bsu + st * (B_SH * 2);
        #pragma unroll
        for (int i = 0; i < 8; i++) {
            int idx = tid + 128 * i;
            int row = idx >> 3, c = idx & 7;
            cp16(au + row * (HPITCH * 2) + c * 16,
                 Ab + (size_t)row * KDIM + k0 + c * 8);
        }
        #pragma unroll
        for (int i = 0; i < 8; i++) {
            int idx = tid + 128 * i;
            int row = idx >> 3, c = idx & 7;
            cp16(bu + row * (HPITCH * 2) + c * 16,
                 W + (size_t)(n0 + row) * KDIM + k0 + c * 8);
        }
        CP_COMMIT();
    };

    float acc[4][8][4];
    #pragma unroll
    for (int i = 0; i < 4; i++)
        #pragma unroll
        for (int j = 0; j < 8; j++)
            #pragma unroll
            for (int q = 0; q < 4; q++) acc[i][j][q] = 0.f;

    load_chunk(0, 0); load_chunk(1, 1);

    for (int j = 0; j < NCHUNK; j++) {
        if (j < NCHUNK - 2) CP_WAIT(1); else CP_WAIT(0);
        __syncthreads();

        if (j + 2 < NCHUNK) load_chunk(j + 2, (j + 2) % GSTG);

        const int st = j % GSTG;
        const uint32_t aS = aL + st * (A_SH * 2);
        const uint32_t bS = bL + st * (B_SH * 2);

        #pragma unroll
        for (int kc = 0; kc < 4; kc++) {
            uint32_t af[4][4], bf[8][2];
            #pragma unroll
            for (int mt = 0; mt < 4; mt++)
                ldsm_x4(af[mt][0], af[mt][1], af[mt][2], af[mt][3],
                        aS + mt * (16 * HPITCH * 2) + kc * 32);
            #pragma unroll
            for (int p = 0; p < 4; p++)
                ldsm_x4(bf[2 * p][0], bf[2 * p][1], bf[2 * p + 1][0], bf[2 * p + 1][1],
                        bS + p * (16 * HPITCH * 2) + kc * 32);
            #pragma unroll
            for (int mt = 0; mt < 4; mt++)
                #pragma unroll
                for (int nt = 0; nt < 8; nt++)
                    mma_f16(acc[mt][nt][0], acc[mt][nt][1], acc[mt][nt][2], acc[mt][nt][3],
                            af[mt][0], af[mt][1], af[mt][2], af[mt][3],
                            bf[nt][0], bf[nt][1]);
        }
    }

    #pragma unroll
    for (int nt = 0; nt < 8; nt++) {
        const int col = n0 + wn * 64 + nt * 8 + 2 * t;
        float bx = 0.f, by = 0.f;
        if (bias) { bx = bias[col]; by = bias[col + 1]; }
        #pragma unroll
        for (int mt = 0; mt < 4; mt++) {
            const int r0 = wm * 64 + mt * 16 + g;
            if constexpr (sizeof(OT) == 2) {
                *(__half2*)((__half*)C + (size_t)r0 * N + col) =
                    __float22half2_rn(make_float2(acc[mt][nt][0] + bx, acc[mt][nt][1] + by));
                *(__half2*)((__half*)C + (size_t)(r0 + 8) * N + col) =
                    __float22half2_rn(make_float2(acc[mt][nt][2] + bx, acc[mt][nt][3] + by));
            } else {
                float2 v0, v1;
                v0.x = acc[mt][nt][0] + bx; v0.y = acc[mt][nt][1] + by;
                v1.x = acc[mt][nt][2] + bx; v1.y = acc[mt][nt][3] + by;
                *(float2*)((float*)C + (size_t)r0 * N + col)       = v0;
                *(float2*)((float*)C + (size_t)(r0 + 8) * N + col) = v1;
            }
        }
    }
}

// ---------------- RMSNorm + RoPE + head split (unchanged layouts from R10) ----------------
__global__ void norm_rope(const float* __restrict__ cosb, const float* __restrict__ sinb,
                          const float* __restrict__ nqw,  const float* __restrict__ nkw,
                          const float* __restrict__ naqw, const float* __restrict__ nakw)
{
    const int s = blockIdx.x / NH, h = blockIdx.x % NH;
    const int which = blockIdx.y;
    const int dh = threadIdx.x;

    __half xh16 = g_qkvh[(size_t)s * ND3 + which * D + h * DH + dh];
    float x = __half2float(xh16);

    if (which == 2) {
        int lane = (dh & 7) * 4 + ((s & 7) >> 1);
        size_t off = (((size_t)h * (S_TOT / 16) + (s >> 4)) * 8 + (dh >> 4)) * 256
                   + (size_t)(lane * 8 + ((dh >> 3) & 1) * 4 + ((s >> 3) & 1) * 2 + (s & 1));
        g_vfh[off] = xh16;
        return;
    }

    __shared__ float sh[128];
    __shared__ float red[4];

    float sq = x * x;
    #pragma unroll
    for (int o = 16; o; o >>= 1) sq += __shfl_xor_sync(0xffffffff, sq, o);
    if ((dh & 31) == 0) red[dh >> 5] = sq;
    __syncthreads();
    float msum = red[0] + red[1] + red[2] + red[3];
    float r = rsqrtf(msum * (1.0f / 128.0f) + EPS);

    const float* w;
    if (which == 0) w = (s < TXT) ? naqw : nqw;
    else            w = (s < TXT) ? nakw : nkw;

    float xn = x * r * w[dh];
    sh[dh] = xn;
    __syncthreads();

    float c  = cosb[s * 64 + (dh >> 1)];
    float sn = sinb[s * 64 + (dh >> 1)];
    float other = sh[dh ^ 1];
    float o = (dh & 1) ? fmaf(xn, c,  other * sn)
                       : fmaf(xn, c, -other * sn);
    __half oh = __float2half_rn(o);

    if (which == 0) {
        int lane = (s & 7) * 4 + ((dh & 7) >> 1);
        int reg  = ((s >> 3) & 1) + 2 * ((dh >> 3) & 1);
        size_t off = (((size_t)h * (S_TOT / 16) + (s >> 4)) * 8 + (dh >> 4)) * 256
                   + (size_t)(lane * 8 + reg * 2 + (dh & 1));
        g_qfh[off] = oh;
    } else {
        int lane = (s & 7) * 4 + ((dh & 7) >> 1);
        size_t off = (((size_t)h * (S_TOT / 8) + (s >> 3)) * 4 + (dh >> 5)) * 256
                   + (size_t)(lane * 8 + ((dh >> 4) & 1) * 4 + ((dh >> 3) & 1) * 2 + (dh & 1));
        g_kfh[off] = oh;
    }
}

// ---------------- Flash attention, fp16 mma.sync, ping-pong pipelined ----------------
// q-tile 128 (8 warps x 16 rows), kv-tile 32, 4-stage K/V.
// Each iteration: QK(j+1) mmas issued FIRST, then softmax(j) (tensor pipe stays
// busy with queued QK work), then PV(j).
#define QT 128
#define KT 32
#define NKV (S_TOT / KT)     // 80
#define FSTG 4
#define FLASH_SMEM ((16384 + FSTG * 4096 + FSTG * 4096) * 2)   // 98304 bytes

extern __shared__ __half hfsm[];

__global__ __launch_bounds__(256, 2)
void flash_f16()
{
    __half* Qs = hfsm;                         // 16384 halves
    __half* Ks = hfsm + 16384;                 // 4 x 4096
    __half* Vs = hfsm + 16384 + FSTG * 4096;   // 4 x 4096

    const int h   = blockIdx.y;
    const int q0  = blockIdx.x * QT;
    const int tid = threadIdx.x;
    const int lane = tid & 31, wid = tid >> 5;
    const int g = lane >> 2, t = lane & 3;

    const __half* Qg = g_qfh + ((size_t)h * (S_TOT / 16) + (q0 >> 4)) * 2048;
    const __half* Kg = g_kfh + (size_t)h * (S_TOT / 8) * 1024;
    const __half* Vg = g_vfh + (size_t)h * (S_TOT / 16) * 2048;

    const uint32_t qs_u = smem_u32(Qs);
    const uint32_t ks_u = smem_u32(Ks);
    const uint32_t vs_u = smem_u32(Vs);

    // Q tile (own commit group)
    #pragma unroll
    for (int i = 0; i < 8; i++)
        cp16(qs_u + (uint32_t)(tid + 256 * i) * 16, Qg + (size_t)(tid + 256 * i) * 8);
    CP_COMMIT();

    auto loadKV = [&](int j, int st) {
        const __half* kp = Kg + (size_t)j * 4096;
        const __half* vp = Vg + (size_t)j * 4096;
        uint32_t ku = ks_u + st * 8192;
        uint32_t vu = vs_u + st * 8192;
        #pragma unroll
        for (int i = 0; i < 2; i++) {
            cp16(ku + (uint32_t)(tid + 256 * i) * 16, kp + (size_t)(tid + 256 * i) * 8);
            cp16(vu + (uint32_t)(tid + 256 * i) * 16, vp + (size_t)(tid + 256 * i) * 8);
        }
        CP_COMMIT();
    };

    // QK^T for one kv-tile: S[16 x 32] per warp, paired K loads
    auto qk_tile = [&](float (&s)[4][4], const __half* Kst) {
        #pragma unroll
        for (int nt = 0; nt < 4; nt++)
            #pragma unroll
            for (int q = 0; q < 4; q++) s[nt][q] = 0.f;
        #pragma unroll
        for (int kc2 = 0; kc2 < 4; kc2++) {
            uint4 a0v = *(const uint4*)(Qs + (wid * 8 + 2 * kc2) * 256 + lane * 8);
            uint4 a1v = *(const uint4*)(Qs + (wid * 8 + 2 * kc2 + 1) * 256 + lane * 8);
            #pragma unroll
            for (int nt = 0; nt < 4; nt++) {
                uint4 kb = *(const uint4*)(Kst + (nt * 4 + kc2) * 256 + lane * 8);
                mma_f16(s[nt][0], s[nt][1], s[nt][2], s[nt][3],
                        a0v.x, a0v.y, a0v.z, a0v.w, kb.x, kb.y);
                mma_f16(s[nt][0], s[nt][1], s[nt][2], s[nt][3],
                        a1v.x, a1v.y, a1v.z, a1v.w, kb.z, kb.w);
            }
        }
    };

    loadKV(0, 0); loadKV(1, 1); loadKV(2, 2);
    CP_WAIT(2);              // Q group + KV0 complete
    __syncthreads();

    float oc[16][4];
    #pragma unroll
    for (int nt = 0; nt < 16; nt++)
        #pragma unroll
        for (int q = 0; q < 4; q++) oc[nt][q] = 0.f;
    float mr0 = -3.4e38f, mr1 = -3.4e38f, lr0 = 0.f, lr1 = 0.f;

    float sc[4][4];
    qk_tile(sc, Ks);         // tile 0, stage 0

    for (int j = 0; j < NKV; j++) {
        if (j <= NKV - 3) CP_WAIT(1); else CP_WAIT(0);
        __syncthreads();     // all warps done reading stage (j+3)&3 (= PV of j-1)
        if (j + 3 < NKV) loadKV(j + 3, (j + 3) & 3);

        // ---- issue QK(j+1) FIRST: tensor pipe stays fed during softmax(j) ----
        float sn[4][4];
        if (j + 1 < NKV) qk_tile(sn, Ks + ((j + 1) & 3) * 4096);

        // ---- online softmax on sc (tile j) ----
        float mx0 = -3.4e38f, mx1 = -3.4e38f;
        #pragma unroll
        for (int nt = 0; nt < 4; nt++) {
            mx0 = fmaxf(mx0, fmaxf(sc[nt][0], sc[nt][1]));
            mx1 = fmaxf(mx1, fmaxf(sc[nt][2], sc[nt][3]));
        }
        mx0 = fmaxf(mx0, __shfl_xor_sync(0xffffffff, mx0, 1));
        mx0 = fmaxf(mx0, __shfl_xor_sync(0xffffffff, mx0, 2));
        mx1 = fmaxf(mx1, __shfl_xor_sync(0xffffffff, mx1, 1));
        mx1 = fmaxf(mx1, __shfl_xor_sync(0xffffffff, mx1, 2));

        float mn0 = fmaxf(mr0, mx0), mn1 = fmaxf(mr1, mx1);
        float al0 = ex2f((mr0 - mn0) * CEXP);
        float al1 = ex2f((mr1 - mn1) * CEXP);
        mr0 = mn0; mr1 = mn1;

        float s0 = 0.f, s1 = 0.f;
        #pragma unroll
        for (int nt = 0; nt < 4; nt++) {
            sc[nt][0] = ex2f((sc[nt][0] - mn0) * CEXP);
            sc[nt][1] = ex2f((sc[nt][1] - mn0) * CEXP);
            sc[nt][2] = ex2f((sc[nt][2] - mn1) * CEXP);
            sc[nt][3] = ex2f((sc[nt][3] - mn1) * CEXP);
            s0 += sc[nt][0] + sc[nt][1];
            s1 += sc[nt][2] + sc[nt][3];
        }
        s0 += __shfl_xor_sync(0xffffffff, s0, 1);
        s0 += __shfl_xor_sync(0xffffffff, s0, 2);
        s1 += __shfl_xor_sync(0xffffffff, s1, 1);
        s1 += __shfl_xor_sync(0xffffffff, s1, 2);
        lr0 = lr0 * al0 + s0;
        lr1 = lr1 * al1 + s1;

        #pragma unroll
        for (int nt = 0; nt < 16; nt++) {
            oc[nt][0] *= al0; oc[nt][1] *= al0;
            oc[nt][2] *= al1; oc[nt][3] *= al1;
        }

        // ---- P @ V (tile j): paired V loads ----
        const __half* Vst = Vs + (j & 3) * 4096;
        #pragma unroll
        for (int kc = 0; kc < 2; kc++) {
            uint32_t a0 = pack_h2(sc[2 * kc][0],     sc[2 * kc][1]);
            uint32_t a1 = pack_h2(sc[2 * kc][2],     sc[2 * kc][3]);
            uint32_t a2 = pack_h2(sc[2 * kc + 1][0], sc[2 * kc + 1][1]);
            uint32_t a3 = pack_h2(sc[2 * kc + 1][2], sc[2 * kc + 1][3]);
            #pragma unroll
            for (int ntp = 0; ntp < 8; ntp++) {
                uint4 vb = *(const uint4*)(Vst + (kc * 8 + ntp) * 256 + lane * 8);
                mma_f16(oc[2 * ntp][0], oc[2 * ntp][1], oc[2 * ntp][2], oc[2 * ntp][3],
                        a0, a1, a2, a3, vb.x, vb.y);
                mma_f16(oc[2 * ntp + 1][0], oc[2 * ntp + 1][1],
                        oc[2 * ntp + 1][2], oc[2 * ntp + 1][3],
                        a0, a1, a2, a3, vb.z, vb.w);
            }
        }

        // rotate score buffers
        if (j + 1 < NKV) {
            #pragma unroll
            for (int nt = 0; nt < 4; nt++)
                #pragma unroll
                for (int q = 0; q < 4; q++) sc[nt][q] = sn[nt][q];
        }
    }

    // ---- normalize + write fp16 (feeds fp16 out-proj) ----
    float li0 = 1.f / lr0, li1 = 1.f / lr1;
    __half* orow0 = g_attnh + (size_t)(q0 + wid * 16 + g) * D + h * DH;
    __half* orow1 = orow0 + (size_t)8 * D;
    #pragma unroll
    for (int nt = 0; nt < 16; nt++) {
        *(__half2*)(orow0 + nt * 8 + 2 * t) =
            __float22half2_rn(make_float2(oc[nt][0] * li0, oc[nt][1] * li0));
        *(__half2*)(orow1 + nt * 8 + 2 * t) =
            __float22half2_rn(make_float2(oc[nt][2] * li1, oc[nt][3] * li1));
    }
}

// ---------------- launch ----------------
extern "C" void kernel_launch(void* const* d_in, const int* in_sizes, int n_in,
                              void* d_out, int out_size)
{
    const float* hidden     = (const float*)d_in[0];
    const float* encoder    = (const float*)d_in[1];
    const float* cosb       = (const float*)d_in[2];
    const float* sinb       = (const float*)d_in[3];
    const float* w_qkv      = (const float*)d_in[4];
    const float* w_add_qkv  = (const float*)d_in[5];
    const float* b_add_qkv  = (const float*)d_in[6];
    const float* norm_q_w   = (const float*)d_in[7];
    const float* norm_k_w   = (const float*)d_in[8];
    const float* norm_aq_w  = (const float*)d_in[9];
    const float* norm_ak_w  = (const float*)d_in[10];
    const float* w_out      = (const float*)d_in[11];
    const float* b_out      = (const float*)d_in[12];
    const float* w_add_out  = (const float*)d_in[13];
    const float* b_add_out  = (const float*)d_in[14];
    float* out = (float*)d_out;

    __half *qkvh, *xh, *wqh, *waqh, *woh, *waoh, *attnh;
    cudaGetSymbolAddress((void**)&qkvh,  g_qkvh);
    cudaGetSymbolAddress((void**)&xh,    g_xh);
    cudaGetSymbolAddress((void**)&wqh,   g_wqkvh);
    cudaGetSymbolAddress((void**)&waqh,  g_waddqkvh);
    cudaGetSymbolAddress((void**)&woh,   g_wouth);
    cudaGetSymbolAddress((void**)&waoh,  g_waddouth);
    cudaGetSymbolAddress((void**)&attnh, g_attnh);

    cudaFuncSetAttribute(flash_f16, cudaFuncAttributeMaxDynamicSharedMemorySize, FLASH_SMEM);
    cudaFuncSetAttribute(gemm_f16<__half>, cudaFuncAttributeMaxDynamicSharedMemorySize, GEMM_SMEM_BYTES);
    cudaFuncSetAttribute(gemm_f16<float>,  cudaFuncAttributeMaxDynamicSharedMemorySize, GEMM_SMEM_BYTES);

    // Launch order: 0 conv_all, 1 gemm qkv, 2 norm_rope, 3 flash (profiled), 4 gemm out
    {
        const int NE = TXT * D / 4, NHd = IMG * D / 4;
        const int NW = ND3 * D / 4, NO = D * D / 4;
        const int TOT = NE + NHd + 2 * NW + 2 * NO;
        conv_all<<<(TOT + 255) / 256, 256>>>(
            (const float4*)encoder, (const float4*)hidden,
            (const float4*)w_qkv, (const float4*)w_add_qkv,
            (const float4*)w_out, (const float4*)w_add_out,
            (__half2*)xh, (__half2*)wqh, (__half2*)waqh,
            (__half2*)woh, (__half2*)waoh);
    }

    gemm_f16<__half><<<dim3(S_TOT / BM, ND3 / BN), 128, GEMM_SMEM_BYTES>>>(
        xh, waqh, wqh, b_add_qkv, nullptr,
        qkvh, qkvh + (size_t)TXT * ND3, TXT, ND3);

    norm_rope<<<dim3(S_TOT * NH, 3), 128>>>(cosb, sinb, norm_q_w, norm_k_w,
                                            norm_aq_w, norm_ak_w);

    flash_f16<<<dim3(S_TOT / QT, NH), 256, FLASH_SMEM>>>();

    gemm_f16<float><<<dim3(S_TOT / BM, D / BN), 128, GEMM_SMEM_BYTES>>>(
        attnh, waoh, woh, b_add_out, b_out,
        out + (size_t)IMG * D, out, TXT, D);
}

// round 12
// speedup vs baseline: 1.0136x; 1.0136x over previous
#include <cuda_runtime.h>
#include <cuda_fp16.h>
#include <math.h>
#include <stdint.h>

#define S_TOT 2560
#define TXT 256
#define IMG 2304
#define D 3072
#define NH 24
#define DH 128
#define ND3 9216
#define KDIM 3072
#define ATT_SCALE 0.08838834764831845f   // 1/sqrt(128)
#define CEXP (1.4426950408889634f * ATT_SCALE)
#define EPS 1e-5f

// ---------------- scratch (device globals: no allocation allowed) ----------------
__device__ __half g_qkvh[(size_t)S_TOT * ND3];
__device__ __half g_qfh[(size_t)NH * S_TOT * DH];   // fragment-packed fp16
__device__ __half g_kfh[(size_t)NH * S_TOT * DH];
__device__ __half g_vfh[(size_t)NH * S_TOT * DH];
__device__ __half g_attnh[(size_t)S_TOT * D];
// fp16 copies of inputs
__device__ __half g_xh[(size_t)S_TOT * D];
__device__ __half g_wqkvh[(size_t)ND3 * D];
__device__ __half g_waddqkvh[(size_t)ND3 * D];
__device__ __half g_wouth[(size_t)D * D];
__device__ __half g_waddouth[(size_t)D * D];

// ================= helpers =================
static __device__ __forceinline__ uint32_t smem_u32(const void* p) {
    uint32_t r;
    asm("{ .reg .u64 t; cvta.to.shared.u64 t, %1; cvt.u32.u64 %0, t; }" : "=r"(r) : "l"(p));
    return r;
}
static __device__ __forceinline__ void cp16(uint32_t dst, const void* src) {
    asm volatile("cp.async.cg.shared.global [%0], [%1], 16;" :: "r"(dst), "l"(src));
}
#define CP_COMMIT() asm volatile("cp.async.commit_group;" ::: "memory")
#define CP_WAIT(n)  asm volatile("cp.async.wait_group %0;" :: "n"(n) : "memory")

static __device__ __forceinline__ void mma_f16(
    float& c0, float& c1, float& c2, float& c3,
    uint32_t a0, uint32_t a1, uint32_t a2, uint32_t a3,
    uint32_t b0, uint32_t b1)
{
    asm volatile(
        "mma.sync.aligned.m16n8k16.row.col.f32.f16.f16.f32 "
        "{%0,%1,%2,%3}, {%4,%5,%6,%7}, {%8,%9}, {%0,%1,%2,%3};"
        : "+f"(c0), "+f"(c1), "+f"(c2), "+f"(c3)
        : "r"(a0), "r"(a1), "r"(a2), "r"(a3), "r"(b0), "r"(b1));
}
static __device__ __forceinline__ void ldsm_x4(
    uint32_t& r0, uint32_t& r1, uint32_t& r2, uint32_t& r3, uint32_t addr)
{
    asm volatile("ldmatrix.sync.aligned.m8n8.x4.shared.b16 {%0,%1,%2,%3}, [%4];"
                 : "=r"(r0), "=r"(r1), "=r"(r2), "=r"(r3) : "r"(addr));
}
static __device__ __forceinline__ uint32_t pack_h2(float x, float y) {
    __half2 h = __float22half2_rn(make_float2(x, y));
    return *reinterpret_cast<uint32_t*>(&h);
}
static __device__ __forceinline__ float ex2f(float x) {
    float r;
    asm("ex2.approx.f32 %0, %1;" : "=f"(r) : "f"(x));
    return r;
}

// ---------------- single merged fp32 -> fp16 conversion pass ----------------
__global__ void conv_all(const float4* __restrict__ enc, const float4* __restrict__ hid,
                         const float4* __restrict__ wq,  const float4* __restrict__ waq,
                         const float4* __restrict__ wo,  const float4* __restrict__ wao,
                         __half2* __restrict__ xh,
                         __half2* __restrict__ wqh, __half2* __restrict__ waqh,
                         __half2* __restrict__ woh, __half2* __restrict__ waoh)
{
    const int NE = TXT * D / 4, NHd = IMG * D / 4;
    const int NW = ND3 * D / 4, NO = D * D / 4;
    const int TOT = NE + NHd + 2 * NW + 2 * NO;
    int i = blockIdx.x * blockDim.x + threadIdx.x;
    if (i >= TOT) return;

    const float4* s; __half2* d; int k;
    if (i < NE)                        { s = enc; d = xh;                      k = i; }
    else if (i < NE + NHd)             { s = hid; d = xh + (size_t)NE * 2;     k = i - NE; }
    else if (i < NE + NHd + NW)        { s = wq;  d = wqh;                     k = i - NE - NHd; }
    else if (i < NE + NHd + 2 * NW)    { s = waq; d = waqh;                    k = i - NE - NHd - NW; }
    else if (i < NE + NHd + 2 * NW + NO){ s = wo; d = woh;                     k = i - NE - NHd - 2 * NW; }
    else                               { s = wao; d = waoh;                    k = i - NE - NHd - 2 * NW - NO; }

    float4 v = s[k];
    d[k * 2]     = __float22half2_rn(make_float2(v.x, v.y));
    d[k * 2 + 1] = __float22half2_rn(make_float2(v.z, v.w));
}

// ================= fp16 mma.sync GEMM (unchanged) =================
#define BM 128
#define BN 128
#define BK 64
#define GSTG 3
#define NCHUNK (KDIM / BK)       // 48
#define HPITCH 72
#define A_SH (BM * HPITCH)
#define B_SH (BN * HPITCH)
#define GEMM_SMEM_BYTES (GSTG * (A_SH + B_SH) * 2)   // 110592

template <typename OT>
__global__ __launch_bounds__(128, 2)
void gemm_f16(const __half* __restrict__ A,
              const __half* __restrict__ W0, const __half* __restrict__ W1,
              const float* __restrict__ b0, const float* __restrict__ b1,
              OT* __restrict__ C0, OT* __restrict__ C1,
              int M0, int N)
{
    extern __shared__ __half hsm[];
    __half* Asm = hsm;
    __half* Bsm = hsm + GSTG * A_SH;

    const int tid  = threadIdx.x;
    const int lane = tid & 31;
    const int wid  = tid >> 5;
    const int wm   = wid >> 1;
    const int wn   = wid & 1;
    const int g    = lane >> 2;
    const int t    = lane & 3;

    const int bm = blockIdx.x, bn = blockIdx.y;
    const int rowbase = bm * BM;
    const int n0 = bn * BN;

    const __half* Ab = A + (size_t)rowbase * KDIM;
    const __half* W; const float* bias; OT* C;
    if (rowbase < M0) { W = W0; bias = b0; C = C0 + (size_t)rowbase * N; }
    else              { W = W1; bias = b1; C = C1 + (size_t)(rowbase - M0) * N; }

    const uint32_t asu = smem_u32(Asm);
    const uint32_t bsu = smem_u32(Bsm);

    const uint32_t aL = asu + (uint32_t)(((wm * 64 + (lane & 15)) * HPITCH
                                          + (lane >> 4) * 8) * 2);
    const uint32_t bL = bsu + (uint32_t)(((wn * 64 + (lane & 7) + (lane >> 4) * 8) * HPITCH
                                          + ((lane >> 3) & 1) * 8) * 2);

    auto load_chunk = [&](int ck, int st) {
        const int k0 = ck * BK;
        const uint32_t au = asu + st * (A_SH * 2);
        const uint32_t bu = bsu + st * (B_SH * 2);
        #pragma unroll
        for (int i = 0; i < 8; i++) {
            int idx = tid + 128 * i;
            int row = idx >> 3, c = idx & 7;
            cp16(au + row * (HPITCH * 2) + c * 16,
                 Ab + (size_t)row * KDIM + k0 + c * 8);
        }
        #pragma unroll
        for (int i = 0; i < 8; i++) {
            int idx = tid + 128 * i;
            int row = idx >> 3, c = idx & 7;
            cp16(bu + row * (HPITCH * 2) + c * 16,
                 W + (size_t)(n0 + row) * KDIM + k0 + c * 8);
        }
        CP_COMMIT();
    };

    float acc[4][8][4];
    #pragma unroll
    for (int i = 0; i < 4; i++)
        #pragma unroll
        for (int j = 0; j < 8; j++)
            #pragma unroll
            for (int q = 0; q < 4; q++) acc[i][j][q] = 0.f;

    load_chunk(0, 0); load_chunk(1, 1);

    for (int j = 0; j < NCHUNK; j++) {
        if (j < NCHUNK - 2) CP_WAIT(1); else CP_WAIT(0);
        __syncthreads();

        if (j + 2 < NCHUNK) load_chunk(j + 2, (j + 2) % GSTG);

        const int st = j % GSTG;
        const uint32_t aS = aL + st * (A_SH * 2);
        const uint32_t bS = bL + st * (B_SH * 2);

        #pragma unroll
        for (int kc = 0; kc < 4; kc++) {
            uint32_t af[4][4], bf[8][2];
            #pragma unroll
            for (int mt = 0; mt < 4; mt++)
                ldsm_x4(af[mt][0], af[mt][1], af[mt][2], af[mt][3],
                        aS + mt * (16 * HPITCH * 2) + kc * 32);
            #pragma unroll
            for (int p = 0; p < 4; p++)
                ldsm_x4(bf[2 * p][0], bf[2 * p][1], bf[2 * p + 1][0], bf[2 * p + 1][1],
                        bS + p * (16 * HPITCH * 2) + kc * 32);
            #pragma unroll
            for (int mt = 0; mt < 4; mt++)
                #pragma unroll
                for (int nt = 0; nt < 8; nt++)
                    mma_f16(acc[mt][nt][0], acc[mt][nt][1], acc[mt][nt][2], acc[mt][nt][3],
                            af[mt][0], af[mt][1], af[mt][2], af[mt][3],
                            bf[nt][0], bf[nt][1]);
        }
    }

    #pragma unroll
    for (int nt = 0; nt < 8; nt++) {
        const int col = n0 + wn * 64 + nt * 8 + 2 * t;
        float bx = 0.f, by = 0.f;
        if (bias) { bx = bias[col]; by = bias[col + 1]; }
        #pragma unroll
        for (int mt = 0; mt < 4; mt++) {
            const int r0 = wm * 64 + mt * 16 + g;
            if constexpr (sizeof(OT) == 2) {
                *(__half2*)((__half*)C + (size_t)r0 * N + col) =
                    __float22half2_rn(make_float2(acc[mt][nt][0] + bx, acc[mt][nt][1] + by));
                *(__half2*)((__half*)C + (size_t)(r0 + 8) * N + col) =
                    __float22half2_rn(make_float2(acc[mt][nt][2] + bx, acc[mt][nt][3] + by));
            } else {
                float2 v0, v1;
                v0.x = acc[mt][nt][0] + bx; v0.y = acc[mt][nt][1] + by;
                v1.x = acc[mt][nt][2] + bx; v1.y = acc[mt][nt][3] + by;
                *(float2*)((float*)C + (size_t)r0 * N + col)       = v0;
                *(float2*)((float*)C + (size_t)(r0 + 8) * N + col) = v1;
            }
        }
    }
}

// ---------------- RMSNorm + RoPE + head split (layouts unchanged from R10) ----------------
__global__ void norm_rope(const float* __restrict__ cosb, const float* __restrict__ sinb,
                          const float* __restrict__ nqw,  const float* __restrict__ nkw,
                          const float* __restrict__ naqw, const float* __restrict__ nakw)
{
    const int s = blockIdx.x / NH, h = blockIdx.x % NH;
    const int which = blockIdx.y;
    const int dh = threadIdx.x;

    __half xh16 = g_qkvh[(size_t)s * ND3 + which * D + h * DH + dh];
    float x = __half2float(xh16);

    if (which == 2) {
        int lane = (dh & 7) * 4 + ((s & 7) >> 1);
        size_t off = (((size_t)h * (S_TOT / 16) + (s >> 4)) * 8 + (dh >> 4)) * 256
                   + (size_t)(lane * 8 + ((dh >> 3) & 1) * 4 + ((s >> 3) & 1) * 2 + (s & 1));
        g_vfh[off] = xh16;
        return;
    }

    __shared__ float sh[128];
    __shared__ float red[4];

    float sq = x * x;
    #pragma unroll
    for (int o = 16; o; o >>= 1) sq += __shfl_xor_sync(0xffffffff, sq, o);
    if ((dh & 31) == 0) red[dh >> 5] = sq;
    __syncthreads();
    float msum = red[0] + red[1] + red[2] + red[3];
    float r = rsqrtf(msum * (1.0f / 128.0f) + EPS);

    const float* w;
    if (which == 0) w = (s < TXT) ? naqw : nqw;
    else            w = (s < TXT) ? nakw : nkw;

    float xn = x * r * w[dh];
    sh[dh] = xn;
    __syncthreads();

    float c  = cosb[s * 64 + (dh >> 1)];
    float sn = sinb[s * 64 + (dh >> 1)];
    float other = sh[dh ^ 1];
    float o = (dh & 1) ? fmaf(xn, c,  other * sn)
                       : fmaf(xn, c, -other * sn);
    __half oh = __float2half_rn(o);

    if (which == 0) {
        int lane = (s & 7) * 4 + ((dh & 7) >> 1);
        int reg  = ((s >> 3) & 1) + 2 * ((dh >> 3) & 1);
        size_t off = (((size_t)h * (S_TOT / 16) + (s >> 4)) * 8 + (dh >> 4)) * 256
                   + (size_t)(lane * 8 + reg * 2 + (dh & 1));
        g_qfh[off] = oh;
    } else {
        int lane = (s & 7) * 4 + ((dh & 7) >> 1);
        size_t off = (((size_t)h * (S_TOT / 8) + (s >> 3)) * 4 + (dh >> 5)) * 256
                   + (size_t)(lane * 8 + ((dh >> 4) & 1) * 4 + ((dh >> 3) & 1) * 2 + (dh & 1));
        g_kfh[off] = oh;
    }
}

// ---------------- Flash attention, fp16 mma.sync (R10 body + lazy rescale) ----------------
// q-tile 128 (8 warps x 16 rows), kv-tile 32, 3-stage K/V, one sync/iter,
// paired uint4 fragment loads, ex2.approx softmax, ballot-guarded O rescale.
#define QT 128
#define KT 32
#define NKV (S_TOT / KT)     // 80
#define FSTG 3
#define FLASH_SMEM ((16384 + FSTG * 4096 + FSTG * 4096) * 2)   // 81920 bytes

extern __shared__ __half hfsm[];

__global__ __launch_bounds__(256, 2)
void flash_f16()
{
    __half* Qs = hfsm;                         // 16384 halves
    __half* Ks = hfsm + 16384;                 // 3 x 4096
    __half* Vs = hfsm + 16384 + FSTG * 4096;   // 3 x 4096

    const int h   = blockIdx.y;
    const int q0  = blockIdx.x * QT;
    const int tid = threadIdx.x;
    const int lane = tid & 31, wid = tid >> 5;
    const int g = lane >> 2, t = lane & 3;

    const __half* Qg = g_qfh + ((size_t)h * (S_TOT / 16) + (q0 >> 4)) * 2048;
    const __half* Kg = g_kfh + (size_t)h * (S_TOT / 8) * 1024;
    const __half* Vg = g_vfh + (size_t)h * (S_TOT / 16) * 2048;

    const uint32_t qs_u = smem_u32(Qs);
    const uint32_t ks_u = smem_u32(Ks);
    const uint32_t vs_u = smem_u32(Vs);

    #pragma unroll
    for (int i = 0; i < 8; i++)
        cp16(qs_u + (uint32_t)(tid + 256 * i) * 16, Qg + (size_t)(tid + 256 * i) * 8);
    CP_COMMIT();

    auto loadKV = [&](int j, int st) {
        const __half* kp = Kg + (size_t)j * 4096;
        const __half* vp = Vg + (size_t)j * 4096;
        uint32_t ku = ks_u + st * 8192;
        uint32_t vu = vs_u + st * 8192;
        #pragma unroll
        for (int i = 0; i < 2; i++) {
            cp16(ku + (uint32_t)(tid + 256 * i) * 16, kp + (size_t)(tid + 256 * i) * 8);
            cp16(vu + (uint32_t)(tid + 256 * i) * 16, vp + (size_t)(tid + 256 * i) * 8);
        }
        CP_COMMIT();
    };
    loadKV(0, 0);
    loadKV(1, 1);

    float oc[16][4];
    #pragma unroll
    for (int nt = 0; nt < 16; nt++)
        #pragma unroll
        for (int q = 0; q < 4; q++) oc[nt][q] = 0.f;
    float mr0 = -3.4e38f, mr1 = -3.4e38f, lr0 = 0.f, lr1 = 0.f;

    for (int j = 0; j < NKV; j++) {
        if (j < NKV - 1) CP_WAIT(1); else CP_WAIT(0);
        __syncthreads();
        if (j + 2 < NKV) loadKV(j + 2, (j + 2) % FSTG);

        const __half* Kst = Ks + (j % FSTG) * 4096;
        const __half* Vst = Vs + (j % FSTG) * 4096;

        // ---- QK^T: S[16 x 32] per warp; paired K loads ----
        float sc[4][4];
        #pragma unroll
        for (int nt = 0; nt < 4; nt++)
            #pragma unroll
            for (int q = 0; q < 4; q++) sc[nt][q] = 0.f;

        #pragma unroll
        for (int kc2 = 0; kc2 < 4; kc2++) {
            uint4 a0v = *(const uint4*)(Qs + (wid * 8 + 2 * kc2) * 256 + lane * 8);
            uint4 a1v = *(const uint4*)(Qs + (wid * 8 + 2 * kc2 + 1) * 256 + lane * 8);
            #pragma unroll
            for (int nt = 0; nt < 4; nt++) {
                uint4 kb = *(const uint4*)(Kst + (nt * 4 + kc2) * 256 + lane * 8);
                mma_f16(sc[nt][0], sc[nt][1], sc[nt][2], sc[nt][3],
                        a0v.x, a0v.y, a0v.z, a0v.w, kb.x, kb.y);
                mma_f16(sc[nt][0], sc[nt][1], sc[nt][2], sc[nt][3],
                        a1v.x, a1v.y, a1v.z, a1v.w, kb.z, kb.w);
            }
        }

        // ---- online softmax (registers; rows g and g+8) ----
        float mx0 = -3.4e38f, mx1 = -3.4e38f;
        #pragma unroll
        for (int nt = 0; nt < 4; nt++) {
            mx0 = fmaxf(mx0, fmaxf(sc[nt][0], sc[nt][1]));
            mx1 = fmaxf(mx1, fmaxf(sc[nt][2], sc[nt][3]));
        }
        mx0 = fmaxf(mx0, __shfl_xor_sync(0xffffffff, mx0, 1));
        mx0 = fmaxf(mx0, __shfl_xor_sync(0xffffffff, mx0, 2));
        mx1 = fmaxf(mx1, __shfl_xor_sync(0xffffffff, mx1, 1));
        mx1 = fmaxf(mx1, __shfl_xor_sync(0xffffffff, mx1, 2));

        float mn0 = fmaxf(mr0, mx0), mn1 = fmaxf(mr1, mx1);
        float al0 = ex2f((mr0 - mn0) * CEXP);
        float al1 = ex2f((mr1 - mn1) * CEXP);
        mr0 = mn0; mr1 = mn1;

        float s0 = 0.f, s1 = 0.f;
        #pragma unroll
        for (int nt = 0; nt < 4; nt++) {
            sc[nt][0] = ex2f((sc[nt][0] - mn0) * CEXP);
            sc[nt][1] = ex2f((sc[nt][1] - mn0) * CEXP);
            sc[nt][2] = ex2f((sc[nt][2] - mn1) * CEXP);
            sc[nt][3] = ex2f((sc[nt][3] - mn1) * CEXP);
            s0 += sc[nt][0] + sc[nt][1];
            s1 += sc[nt][2] + sc[nt][3];
        }
        s0 += __shfl_xor_sync(0xffffffff, s0, 1);
        s0 += __shfl_xor_sync(0xffffffff, s0, 2);
        s1 += __shfl_xor_sync(0xffffffff, s1, 1);
        s1 += __shfl_xor_sync(0xffffffff, s1, 2);
        lr0 = lr0 * al0 + s0;
        lr1 = lr1 * al1 + s1;

        // ---- lazy O rescale: skip when every lane's al == 1.0 (bit-identical) ----
        if (__ballot_sync(0xffffffff, (al0 != 1.f) | (al1 != 1.f))) {
            #pragma unroll
            for (int nt = 0; nt < 16; nt++) {
                oc[nt][0] *= al0; oc[nt][1] *= al0;
                oc[nt][2] *= al1; oc[nt][3] *= al1;
            }
        }

        // ---- P @ V: P refragmented in registers; paired V loads ----
        #pragma unroll
        for (int kc = 0; kc < 2; kc++) {
            uint32_t a0 = pack_h2(sc[2 * kc][0],     sc[2 * kc][1]);
            uint32_t a1 = pack_h2(sc[2 * kc][2],     sc[2 * kc][3]);
            uint32_t a2 = pack_h2(sc[2 * kc + 1][0], sc[2 * kc + 1][1]);
            uint32_t a3 = pack_h2(sc[2 * kc + 1][2], sc[2 * kc + 1][3]);
            #pragma unroll
            for (int ntp = 0; ntp < 8; ntp++) {
                uint4 vb = *(const uint4*)(Vst + (kc * 8 + ntp) * 256 + lane * 8);
                mma_f16(oc[2 * ntp][0], oc[2 * ntp][1], oc[2 * ntp][2], oc[2 * ntp][3],
                        a0, a1, a2, a3, vb.x, vb.y);
                mma_f16(oc[2 * ntp + 1][0], oc[2 * ntp + 1][1],
                        oc[2 * ntp + 1][2], oc[2 * ntp + 1][3],
                        a0, a1, a2, a3, vb.z, vb.w);
            }
        }
    }

    // ---- normalize + write fp16 (feeds fp16 out-proj) ----
    float li0 = 1.f / lr0, li1 = 1.f / lr1;
    __half* orow0 = g_attnh + (size_t)(q0 + wid * 16 + g) * D + h * DH;
    __half* orow1 = orow0 + (size_t)8 * D;
    #pragma unroll
    for (int nt = 0; nt < 16; nt++) {
        *(__half2*)(orow0 + nt * 8 + 2 * t) =
            __float22half2_rn(make_float2(oc[nt][0] * li0, oc[nt][1] * li0));
        *(__half2*)(orow1 + nt * 8 + 2 * t) =
            __float22half2_rn(make_float2(oc[nt][2] * li1, oc[nt][3] * li1));
    }
}

// ---------------- launch ----------------
extern "C" void kernel_launch(void* const* d_in, const int* in_sizes, int n_in,
                              void* d_out, int out_size)
{
    const float* hidden     = (const float*)d_in[0];
    const float* encoder    = (const float*)d_in[1];
    const float* cosb       = (const float*)d_in[2];
    const float* sinb       = (const float*)d_in[3];
    const float* w_qkv      = (const float*)d_in[4];
    const float* w_add_qkv  = (const float*)d_in[5];
    const float* b_add_qkv  = (const float*)d_in[6];
    const float* norm_q_w   = (const float*)d_in[7];
    const float* norm_k_w   = (const float*)d_in[8];
    const float* norm_aq_w  = (const float*)d_in[9];
    const float* norm_ak_w  = (const float*)d_in[10];
    const float* w_out      = (const float*)d_in[11];
    const float* b_out      = (const float*)d_in[12];
    const float* w_add_out  = (const float*)d_in[13];
    const float* b_add_out  = (const float*)d_in[14];
    float* out = (float*)d_out;

    __half *qkvh, *xh, *wqh, *waqh, *woh, *waoh, *attnh;
    cudaGetSymbolAddress((void**)&qkvh,  g_qkvh);
    cudaGetSymbolAddress((void**)&xh,    g_xh);
    cudaGetSymbolAddress((void**)&wqh,   g_wqkvh);
    cudaGetSymbolAddress((void**)&waqh,  g_waddqkvh);
    cudaGetSymbolAddress((void**)&woh,   g_wouth);
    cudaGetSymbolAddress((void**)&waoh,  g_waddouth);
    cudaGetSymbolAddress((void**)&attnh, g_attnh);

    cudaFuncSetAttribute(flash_f16, cudaFuncAttributeMaxDynamicSharedMemorySize, FLASH_SMEM);
    cudaFuncSetAttribute(gemm_f16<__half>, cudaFuncAttributeMaxDynamicSharedMemorySize, GEMM_SMEM_BYTES);
    cudaFuncSetAttribute(gemm_f16<float>,  cudaFuncAttributeMaxDynamicSharedMemorySize, GEMM_SMEM_BYTES);

    // Launch order: 0 conv_all, 1 gemm qkv, 2 norm_rope, 3 flash (profiled), 4 gemm out
    {
        const int NE = TXT * D / 4, NHd = IMG * D / 4;
        const int NW = ND3 * D / 4, NO = D * D / 4;
        const int TOT = NE + NHd + 2 * NW + 2 * NO;
        conv_all<<<(TOT + 255) / 256, 256>>>(
            (const float4*)encoder, (const float4*)hidden,
            (const float4*)w_qkv, (const float4*)w_add_qkv,
            (const float4*)w_out, (const float4*)w_add_out,
            (__half2*)xh, (__half2*)wqh, (__half2*)waqh,
            (__half2*)woh, (__half2*)waoh);
    }

    gemm_f16<__half><<<dim3(S_TOT / BM, ND3 / BN), 128, GEMM_SMEM_BYTES>>>(
        xh, waqh, wqh, b_add_qkv, nullptr,
        qkvh, qkvh + (size_t)TXT * ND3, TXT, ND3);

    norm_rope<<<dim3(S_TOT * NH, 3), 128>>>(cosb, sinb, norm_q_w, norm_k_w,
                                            norm_aq_w, norm_ak_w);

    flash_f16<<<dim3(S_TOT / QT, NH), 256, FLASH_SMEM>>>();

    gemm_f16<float><<<dim3(S_TOT / BM, D / BN), 128, GEMM_SMEM_BYTES>>>(
        attnh, waoh, woh, b_add_out, b_out,
        out + (size_t)IMG * D, out, TXT, D);
}

// round 13
// speedup vs baseline: 1.0971x; 1.0824x over previous
#include <cuda_runtime.h>
#include <cuda_fp16.h>
#include <math.h>
#include <stdint.h>

#define S_TOT 2560
#define TXT 256
#define IMG 2304
#define D 3072
#define NH 24
#define DH 128
#define ND3 9216
#define KDIM 3072
#define ATT_SCALE 0.08838834764831845f   // 1/sqrt(128)
#define CEXP (1.4426950408889634f * ATT_SCALE)
#define EPS 1e-5f

// ---------------- scratch (device globals: no allocation allowed) ----------------
__device__ __half g_qfh[(size_t)NH * S_TOT * DH];   // fragment-packed fp16
__device__ __half g_kfh[(size_t)NH * S_TOT * DH];
__device__ __half g_vfh[(size_t)NH * S_TOT * DH];
__device__ __half g_attnh[(size_t)S_TOT * D];
// fp16 copies of inputs
__device__ __half g_xh[(size_t)S_TOT * D];
__device__ __half g_wqkvh[(size_t)ND3 * D];
__device__ __half g_waddqkvh[(size_t)ND3 * D];
__device__ __half g_wouth[(size_t)D * D];
__device__ __half g_waddouth[(size_t)D * D];

// ================= helpers =================
static __device__ __forceinline__ uint32_t smem_u32(const void* p) {
    uint32_t r;
    asm("{ .reg .u64 t; cvta.to.shared.u64 t, %1; cvt.u32.u64 %0, t; }" : "=r"(r) : "l"(p));
    return r;
}
static __device__ __forceinline__ void cp16(uint32_t dst, const void* src) {
    asm volatile("cp.async.cg.shared.global [%0], [%1], 16;" :: "r"(dst), "l"(src));
}
#define CP_COMMIT() asm volatile("cp.async.commit_group;" ::: "memory")
#define CP_WAIT(n)  asm volatile("cp.async.wait_group %0;" :: "n"(n) : "memory")

static __device__ __forceinline__ void mma_f16(
    float& c0, float& c1, float& c2, float& c3,
    uint32_t a0, uint32_t a1, uint32_t a2, uint32_t a3,
    uint32_t b0, uint32_t b1)
{
    asm volatile(
        "mma.sync.aligned.m16n8k16.row.col.f32.f16.f16.f32 "
        "{%0,%1,%2,%3}, {%4,%5,%6,%7}, {%8,%9}, {%0,%1,%2,%3};"
        : "+f"(c0), "+f"(c1), "+f"(c2), "+f"(c3)
        : "r"(a0), "r"(a1), "r"(a2), "r"(a3), "r"(b0), "r"(b1));
}
static __device__ __forceinline__ void ldsm_x4(
    uint32_t& r0, uint32_t& r1, uint32_t& r2, uint32_t& r3, uint32_t addr)
{
    asm volatile("ldmatrix.sync.aligned.m8n8.x4.shared.b16 {%0,%1,%2,%3}, [%4];"
                 : "=r"(r0), "=r"(r1), "=r"(r2), "=r"(r3) : "r"(addr));
}
static __device__ __forceinline__ uint32_t pack_h2(float x, float y) {
    __half2 h = __float22half2_rn(make_float2(x, y));
    return *reinterpret_cast<uint32_t*>(&h);
}
static __device__ __forceinline__ float ex2f(float x) {
    float r;
    asm("ex2.approx.f32 %0, %1;" : "=f"(r) : "f"(x));
    return r;
}

// ---------------- single merged fp32 -> fp16 conversion pass ----------------
__global__ void conv_all(const float4* __restrict__ enc, const float4* __restrict__ hid,
                         const float4* __restrict__ wq,  const float4* __restrict__ waq,
                         const float4* __restrict__ wo,  const float4* __restrict__ wao,
                         __half2* __restrict__ xh,
                         __half2* __restrict__ wqh, __half2* __restrict__ waqh,
                         __half2* __restrict__ woh, __half2* __restrict__ waoh)
{
    const int NE = TXT * D / 4, NHd = IMG * D / 4;
    const int NW = ND3 * D / 4, NO = D * D / 4;
    const int TOT = NE + NHd + 2 * NW + 2 * NO;
    int i = blockIdx.x * blockDim.x + threadIdx.x;
    if (i >= TOT) return;

    const float4* s; __half2* d; int k;
    if (i < NE)                        { s = enc; d = xh;                      k = i; }
    else if (i < NE + NHd)             { s = hid; d = xh + (size_t)NE * 2;     k = i - NE; }
    else if (i < NE + NHd + NW)        { s = wq;  d = wqh;                     k = i - NE - NHd; }
    else if (i < NE + NHd + 2 * NW)    { s = waq; d = waqh;                    k = i - NE - NHd - NW; }
    else if (i < NE + NHd + 2 * NW + NO){ s = wo; d = woh;                     k = i - NE - NHd - 2 * NW; }
    else                               { s = wao; d = waoh;                    k = i - NE - NHd - 2 * NW - NO; }

    float4 v = s[k];
    d[k * 2]     = __float22half2_rn(make_float2(v.x, v.y));
    d[k * 2 + 1] = __float22half2_rn(make_float2(v.z, v.w));
}

// ================= fp16 mma.sync GEMM common config =================
#define BM 128
#define BN 128
#define BK 64
#define GSTG 3
#define NCHUNK (KDIM / BK)       // 48
#define HPITCH 72
#define A_SH (BM * HPITCH)
#define B_SH (BN * HPITCH)
#define GEMM_SMEM_BYTES (GSTG * (A_SH + B_SH) * 2)   // 110592

// ---- shared mainloop macro-ish structure is duplicated in the two kernels ----

// ================= generic GEMM (out-proj): C = A @ W^T + bias, fp32 out =================
__global__ __launch_bounds__(128, 2)
void gemm_f16o(const __half* __restrict__ A,
               const __half* __restrict__ W0, const __half* __restrict__ W1,
               const float* __restrict__ b0, const float* __restrict__ b1,
               float* __restrict__ C0, float* __restrict__ C1,
               int M0, int N)
{
    extern __shared__ __half hsm[];
    __half* Asm = hsm;
    __half* Bsm = hsm + GSTG * A_SH;

    const int tid  = threadIdx.x;
    const int lane = tid & 31;
    const int wid  = tid >> 5;
    const int wm   = wid >> 1;
    const int wn   = wid & 1;
    const int g    = lane >> 2;
    const int t    = lane & 3;

    const int bm = blockIdx.x, bn = blockIdx.y;
    const int rowbase = bm * BM;
    const int n0 = bn * BN;

    const __half* Ab = A + (size_t)rowbase * KDIM;
    const __half* W; const float* bias; float* C;
    if (rowbase < M0) { W = W0; bias = b0; C = C0 + (size_t)rowbase * N; }
    else              { W = W1; bias = b1; C = C1 + (size_t)(rowbase - M0) * N; }

    const uint32_t asu = smem_u32(Asm);
    const uint32_t bsu = smem_u32(Bsm);

    const uint32_t aL = asu + (uint32_t)(((wm * 64 + (lane & 15)) * HPITCH
                                          + (lane >> 4) * 8) * 2);
    const uint32_t bL = bsu + (uint32_t)(((wn * 64 + (lane & 7) + (lane >> 4) * 8) * HPITCH
                                          + ((lane >> 3) & 1) * 8) * 2);

    auto load_chunk = [&](int ck, int st) {
        const int k0 = ck * BK;
        const uint32_t au = asu + st * (A_SH * 2);
        const uint32_t bu = bsu + st * (B_SH * 2);
        #pragma unroll
        for (int i = 0; i < 8; i++) {
            int idx = tid + 128 * i;
            int row = idx >> 3, c = idx & 7;
            cp16(au + row * (HPITCH * 2) + c * 16,
                 Ab + (size_t)row * KDIM + k0 + c * 8);
        }
        #pragma unroll
        for (int i = 0; i < 8; i++) {
            int idx = tid + 128 * i;
            int row = idx >> 3, c = idx & 7;
            cp16(bu + row * (HPITCH * 2) + c * 16,
                 W + (size_t)(n0 + row) * KDIM + k0 + c * 8);
        }
        CP_COMMIT();
    };

    float acc[4][8][4];
    #pragma unroll
    for (int i = 0; i < 4; i++)
        #pragma unroll
        for (int j = 0; j < 8; j++)
            #pragma unroll
            for (int q = 0; q < 4; q++) acc[i][j][q] = 0.f;

    load_chunk(0, 0); load_chunk(1, 1);

    for (int j = 0; j < NCHUNK; j++) {
        if (j < NCHUNK - 2) CP_WAIT(1); else CP_WAIT(0);
        __syncthreads();

        if (j + 2 < NCHUNK) load_chunk(j + 2, (j + 2) % GSTG);

        const int st = j % GSTG;
        const uint32_t aS = aL + st * (A_SH * 2);
        const uint32_t bS = bL + st * (B_SH * 2);

        #pragma unroll
        for (int kc = 0; kc < 4; kc++) {
            uint32_t af[4][4], bf[8][2];
            #pragma unroll
            for (int mt = 0; mt < 4; mt++)
                ldsm_x4(af[mt][0], af[mt][1], af[mt][2], af[mt][3],
                        aS + mt * (16 * HPITCH * 2) + kc * 32);
            #pragma unroll
            for (int p = 0; p < 4; p++)
                ldsm_x4(bf[2 * p][0], bf[2 * p][1], bf[2 * p + 1][0], bf[2 * p + 1][1],
                        bS + p * (16 * HPITCH * 2) + kc * 32);
            #pragma unroll
            for (int mt = 0; mt < 4; mt++)
                #pragma unroll
                for (int nt = 0; nt < 8; nt++)
                    mma_f16(acc[mt][nt][0], acc[mt][nt][1], acc[mt][nt][2], acc[mt][nt][3],
                            af[mt][0], af[mt][1], af[mt][2], af[mt][3],
                            bf[nt][0], bf[nt][1]);
        }
    }

    #pragma unroll
    for (int nt = 0; nt < 8; nt++) {
        const int col = n0 + wn * 64 + nt * 8 + 2 * t;
        float bx = bias[col], by = bias[col + 1];
        #pragma unroll
        for (int mt = 0; mt < 4; mt++) {
            const int r0 = wm * 64 + mt * 16 + g;
            float2 v0, v1;
            v0.x = acc[mt][nt][0] + bx; v0.y = acc[mt][nt][1] + by;
            v1.x = acc[mt][nt][2] + bx; v1.y = acc[mt][nt][3] + by;
            *(float2*)(C + (size_t)r0 * N + col)       = v0;
            *(float2*)(C + (size_t)(r0 + 8) * N + col) = v1;
        }
    }
}

// ================= QKV GEMM with fused bias + RMSNorm + RoPE + fragment-packed scatter =================
__global__ __launch_bounds__(128, 2)
void gemm_qkv_fused(const __half* __restrict__ A,
                    const __half* __restrict__ W0, const __half* __restrict__ W1,
                    const float* __restrict__ b0,   // enc bias (img has none)
                    int M0,
                    const float* __restrict__ cosb, const float* __restrict__ sinb,
                    const float* __restrict__ nqw,  const float* __restrict__ nkw,
                    const float* __restrict__ naqw, const float* __restrict__ nakw)
{
    extern __shared__ __half hsm[];
    __half* Asm = hsm;
    __half* Bsm = hsm + GSTG * A_SH;

    const int tid  = threadIdx.x;
    const int lane = tid & 31;
    const int wid  = tid >> 5;
    const int wm   = wid >> 1;
    const int wn   = wid & 1;
    const int g    = lane >> 2;
    const int t    = lane & 3;

    const int bm = blockIdx.x, bn = blockIdx.y;
    const int rowbase = bm * BM;
    const int n0 = bn * BN;

    const __half* Ab = A + (size_t)rowbase * KDIM;
    const bool is_enc = (rowbase < M0);
    const __half* W = is_enc ? W0 : W1;
    const float* bias = is_enc ? b0 : nullptr;

    const uint32_t asu = smem_u32(Asm);
    const uint32_t bsu = smem_u32(Bsm);

    const uint32_t aL = asu + (uint32_t)(((wm * 64 + (lane & 15)) * HPITCH
                                          + (lane >> 4) * 8) * 2);
    const uint32_t bL = bsu + (uint32_t)(((wn * 64 + (lane & 7) + (lane >> 4) * 8) * HPITCH
                                          + ((lane >> 3) & 1) * 8) * 2);

    auto load_chunk = [&](int ck, int st) {
        const int k0 = ck * BK;
        const uint32_t au = asu + st * (A_SH * 2);
        const uint32_t bu = bsu + st * (B_SH * 2);
        #pragma unroll
        for (int i = 0; i < 8; i++) {
            int idx = tid + 128 * i;
            int row = idx >> 3, c = idx & 7;
            cp16(au + row * (HPITCH * 2) + c * 16,
                 Ab + (size_t)row * KDIM + k0 + c * 8);
        }
        #pragma unroll
        for (int i = 0; i < 8; i++) {
            int idx = tid + 128 * i;
            int row = idx >> 3, c = idx & 7;
            cp16(bu + row * (HPITCH * 2) + c * 16,
                 W + (size_t)(n0 + row) * KDIM + k0 + c * 8);
        }
        CP_COMMIT();
    };

    float acc[4][8][4];
    #pragma unroll
    for (int i = 0; i < 4; i++)
        #pragma unroll
        for (int j = 0; j < 8; j++)
            #pragma unroll
            for (int q = 0; q < 4; q++) acc[i][j][q] = 0.f;

    load_chunk(0, 0); load_chunk(1, 1);

    for (int j = 0; j < NCHUNK; j++) {
        if (j < NCHUNK - 2) CP_WAIT(1); else CP_WAIT(0);
        __syncthreads();

        if (j + 2 < NCHUNK) load_chunk(j + 2, (j + 2) % GSTG);

        const int st = j % GSTG;
        const uint32_t aS = aL + st * (A_SH * 2);
        const uint32_t bS = bL + st * (B_SH * 2);

        #pragma unroll
        for (int kc = 0; kc < 4; kc++) {
            uint32_t af[4][4], bf[8][2];
            #pragma unroll
            for (int mt = 0; mt < 4; mt++)
                ldsm_x4(af[mt][0], af[mt][1], af[mt][2], af[mt][3],
                        aS + mt * (16 * HPITCH * 2) + kc * 32);
            #pragma unroll
            for (int p = 0; p < 4; p++)
                ldsm_x4(bf[2 * p][0], bf[2 * p][1], bf[2 * p + 1][0], bf[2 * p + 1][1],
                        bS + p * (16 * HPITCH * 2) + kc * 32);
            #pragma unroll
            for (int mt = 0; mt < 4; mt++)
                #pragma unroll
                for (int nt = 0; nt < 8; nt++)
                    mma_f16(acc[mt][nt][0], acc[mt][nt][1], acc[mt][nt][2], acc[mt][nt][3],
                            af[mt][0], af[mt][1], af[mt][2], af[mt][3],
                            bf[nt][0], bf[nt][1]);
        }
    }

    // ================= fused epilogue =================
    const int which = n0 / D;                     // 0=q, 1=k, 2=v (CTA-uniform)
    const int head  = (n0 - which * D) / DH;      // CTA-uniform

    // bias (enc rows only)
    if (bias) {
        #pragma unroll
        for (int nt = 0; nt < 8; nt++) {
            const int col = n0 + wn * 64 + nt * 8 + 2 * t;
            float bx = bias[col], by = bias[col + 1];
            #pragma unroll
            for (int mt = 0; mt < 4; mt++) {
                acc[mt][nt][0] += bx; acc[mt][nt][1] += by;
                acc[mt][nt][2] += bx; acc[mt][nt][3] += by;
            }
        }
    }

    float rms[4][2];
    if (which < 2) {
        __syncthreads();                       // all warps out of mainloop smem
        float* red = (float*)hsm;              // [2][128]
        #pragma unroll
        for (int mt = 0; mt < 4; mt++) {
            float s0 = 0.f, s1 = 0.f;
            #pragma unroll
            for (int nt = 0; nt < 8; nt++) {
                s0 += acc[mt][nt][0] * acc[mt][nt][0] + acc[mt][nt][1] * acc[mt][nt][1];
                s1 += acc[mt][nt][2] * acc[mt][nt][2] + acc[mt][nt][3] * acc[mt][nt][3];
            }
            s0 += __shfl_xor_sync(0xffffffff, s0, 1);
            s0 += __shfl_xor_sync(0xffffffff, s0, 2);
            s1 += __shfl_xor_sync(0xffffffff, s1, 1);
            s1 += __shfl_xor_sync(0xffffffff, s1, 2);
            if (t == 0) {
                red[wn * 128 + wm * 64 + mt * 16 + g]     = s0;
                red[wn * 128 + wm * 64 + mt * 16 + g + 8] = s1;
            }
        }
        __syncthreads();
        #pragma unroll
        for (int mt = 0; mt < 4; mt++) {
            int r = wm * 64 + mt * 16 + g;
            rms[mt][0] = rsqrtf((red[r] + red[128 + r]) * (1.0f / 128.0f) + EPS);
            rms[mt][1] = rsqrtf((red[r + 8] + red[128 + r + 8]) * (1.0f / 128.0f) + EPS);
        }
    }

    const float* wnorm = (which == 0) ? (is_enc ? naqw : nqw)
                                      : (is_enc ? nakw : nkw);

    #pragma unroll
    for (int nt = 0; nt < 8; nt++) {
        const int dh0 = wn * 64 + nt * 8 + 2 * t;   // even
        float w0 = 0.f, w1 = 0.f;
        if (which < 2) { w0 = wnorm[dh0]; w1 = wnorm[dh0 + 1]; }

        #pragma unroll
        for (int mt = 0; mt < 4; mt++) {
            const int s_lo = rowbase + wm * 64 + mt * 16 + g;
            const int s_hi = s_lo + 8;

            if (which == 2) {
                // V: bias only, fragment-packed scatter (2 half stores per row)
                const int lane0 = (dh0 & 7) * 4 + ((s_lo & 7) >> 1);
                const int lane1 = ((dh0 + 1) & 7) * 4 + ((s_lo & 7) >> 1);
                size_t base_lo = (((size_t)head * (S_TOT / 16) + (s_lo >> 4)) * 8 + (dh0 >> 4)) * 256;
                size_t base_hi = (((size_t)head * (S_TOT / 16) + (s_hi >> 4)) * 8 + (dh0 >> 4)) * 256;
                int sub_lo = ((dh0 >> 3) & 1) * 4 + ((s_lo >> 3) & 1) * 2 + (s_lo & 1);
                int sub_hi = ((dh0 >> 3) & 1) * 4 + ((s_hi >> 3) & 1) * 2 + (s_hi & 1);
                g_vfh[base_lo + lane0 * 8 + sub_lo] = __float2half_rn(acc[mt][nt][0]);
                g_vfh[base_lo + lane1 * 8 + sub_lo] = __float2half_rn(acc[mt][nt][1]);
                g_vfh[base_hi + lane0 * 8 + sub_hi] = __float2half_rn(acc[mt][nt][2]);
                g_vfh[base_hi + lane1 * 8 + sub_hi] = __float2half_rn(acc[mt][nt][3]);
                continue;
            }

            // RMSNorm + RoPE, rows lo and hi
            float c_lo = cosb[s_lo * 64 + (dh0 >> 1)], sn_lo = sinb[s_lo * 64 + (dh0 >> 1)];
            float c_hi = cosb[s_hi * 64 + (dh0 >> 1)], sn_hi = sinb[s_hi * 64 + (dh0 >> 1)];

            float xa = acc[mt][nt][0] * rms[mt][0] * w0;
            float xb = acc[mt][nt][1] * rms[mt][0] * w1;
            float o0 = fmaf(xa, c_lo, -(xb * sn_lo));
            float o1 = fmaf(xb, c_lo,  (xa * sn_lo));

            float ya = acc[mt][nt][2] * rms[mt][1] * w0;
            float yb = acc[mt][nt][3] * rms[mt][1] * w1;
            float p0 = fmaf(ya, c_hi, -(yb * sn_hi));
            float p1 = fmaf(yb, c_hi,  (ya * sn_hi));

            const int laneq = (s_lo & 7) * 4 + ((dh0 & 7) >> 1);  // same for s_hi (s&7 differs by 8 -> same low3)
            if (which == 0) {
                int reg_lo = ((s_lo >> 3) & 1) + 2 * ((dh0 >> 3) & 1);
                int reg_hi = ((s_hi >> 3) & 1) + 2 * ((dh0 >> 3) & 1);
                size_t off_lo = (((size_t)head * (S_TOT / 16) + (s_lo >> 4)) * 8 + (dh0 >> 4)) * 256
                              + (size_t)(laneq * 8 + reg_lo * 2);
                size_t off_hi = (((size_t)head * (S_TOT / 16) + (s_hi >> 4)) * 8 + (dh0 >> 4)) * 256
                              + (size_t)(laneq * 8 + reg_hi * 2);
                *(__half2*)(g_qfh + off_lo) = __float22half2_rn(make_float2(o0, o1));
                *(__half2*)(g_qfh + off_hi) = __float22half2_rn(make_float2(p0, p1));
            } else {
                int sub = ((dh0 >> 4) & 1) * 4 + ((dh0 >> 3) & 1) * 2;
                size_t off_lo = (((size_t)head * (S_TOT / 8) + (s_lo >> 3)) * 4 + (dh0 >> 5)) * 256
                              + (size_t)(laneq * 8 + sub);
                size_t off_hi = (((size_t)head * (S_TOT / 8) + (s_hi >> 3)) * 4 + (dh0 >> 5)) * 256
                              + (size_t)(laneq * 8 + sub);
                *(__half2*)(g_kfh + off_lo) = __float22half2_rn(make_float2(o0, o1));
                *(__half2*)(g_kfh + off_hi) = __float22half2_rn(make_float2(p0, p1));
            }
        }
    }
}

// ---------------- Flash attention, fp16 mma.sync (exact R10 body) ----------------
#define QT 128
#define KT 32
#define NKV (S_TOT / KT)     // 80
#define FSTG 3
#define FLASH_SMEM ((16384 + FSTG * 4096 + FSTG * 4096) * 2)   // 81920 bytes

extern __shared__ __half hfsm[];

__global__ __launch_bounds__(256, 2)
void flash_f16()
{
    __half* Qs = hfsm;
    __half* Ks = hfsm + 16384;
    __half* Vs = hfsm + 16384 + FSTG * 4096;

    const int h   = blockIdx.y;
    const int q0  = blockIdx.x * QT;
    const int tid = threadIdx.x;
    const int lane = tid & 31, wid = tid >> 5;
    const int g = lane >> 2, t = lane & 3;

    const __half* Qg = g_qfh + ((size_t)h * (S_TOT / 16) + (q0 >> 4)) * 2048;
    const __half* Kg = g_kfh + (size_t)h * (S_TOT / 8) * 1024;
    const __half* Vg = g_vfh + (size_t)h * (S_TOT / 16) * 2048;

    const uint32_t qs_u = smem_u32(Qs);
    const uint32_t ks_u = smem_u32(Ks);
    const uint32_t vs_u = smem_u32(Vs);

    #pragma unroll
    for (int i = 0; i < 8; i++)
        cp16(qs_u + (uint32_t)(tid + 256 * i) * 16, Qg + (size_t)(tid + 256 * i) * 8);
    CP_COMMIT();

    auto loadKV = [&](int j, int st) {
        const __half* kp = Kg + (size_t)j * 4096;
        const __half* vp = Vg + (size_t)j * 4096;
        uint32_t ku = ks_u + st * 8192;
        uint32_t vu = vs_u + st * 8192;
        #pragma unroll
        for (int i = 0; i < 2; i++) {
            cp16(ku + (uint32_t)(tid + 256 * i) * 16, kp + (size_t)(tid + 256 * i) * 8);
            cp16(vu + (uint32_t)(tid + 256 * i) * 16, vp + (size_t)(tid + 256 * i) * 8);
        }
        CP_COMMIT();
    };
    loadKV(0, 0);
    loadKV(1, 1);

    float oc[16][4];
    #pragma unroll
    for (int nt = 0; nt < 16; nt++)
        #pragma unroll
        for (int q = 0; q < 4; q++) oc[nt][q] = 0.f;
    float mr0 = -3.4e38f, mr1 = -3.4e38f, lr0 = 0.f, lr1 = 0.f;

    for (int j = 0; j < NKV; j++) {
        if (j < NKV - 1) CP_WAIT(1); else CP_WAIT(0);
        __syncthreads();
        if (j + 2 < NKV) loadKV(j + 2, (j + 2) % FSTG);

        const __half* Kst = Ks + (j % FSTG) * 4096;
        const __half* Vst = Vs + (j % FSTG) * 4096;

        float sc[4][4];
        #pragma unroll
        for (int nt = 0; nt < 4; nt++)
            #pragma unroll
            for (int q = 0; q < 4; q++) sc[nt][q] = 0.f;

        #pragma unroll
        for (int kc2 = 0; kc2 < 4; kc2++) {
            uint4 a0v = *(const uint4*)(Qs + (wid * 8 + 2 * kc2) * 256 + lane * 8);
            uint4 a1v = *(const uint4*)(Qs + (wid * 8 + 2 * kc2 + 1) * 256 + lane * 8);
            #pragma unroll
            for (int nt = 0; nt < 4; nt++) {
                uint4 kb = *(const uint4*)(Kst + (nt * 4 + kc2) * 256 + lane * 8);
                mma_f16(sc[nt][0], sc[nt][1], sc[nt][2], sc[nt][3],
                        a0v.x, a0v.y, a0v.z, a0v.w, kb.x, kb.y);
                mma_f16(sc[nt][0], sc[nt][1], sc[nt][2], sc[nt][3],
                        a1v.x, a1v.y, a1v.z, a1v.w, kb.z, kb.w);
            }
        }

        float mx0 = -3.4e38f, mx1 = -3.4e38f;
        #pragma unroll
        for (int nt = 0; nt < 4; nt++) {
            mx0 = fmaxf(mx0, fmaxf(sc[nt][0], sc[nt][1]));
            mx1 = fmaxf(mx1, fmaxf(sc[nt][2], sc[nt][3]));
        }
        mx0 = fmaxf(mx0, __shfl_xor_sync(0xffffffff, mx0, 1));
        mx0 = fmaxf(mx0, __shfl_xor_sync(0xffffffff, mx0, 2));
        mx1 = fmaxf(mx1, __shfl_xor_sync(0xffffffff, mx1, 1));
        mx1 = fmaxf(mx1, __shfl_xor_sync(0xffffffff, mx1, 2));

        float mn0 = fmaxf(mr0, mx0), mn1 = fmaxf(mr1, mx1);
        float al0 = ex2f((mr0 - mn0) * CEXP);
        float al1 = ex2f((mr1 - mn1) * CEXP);
        mr0 = mn0; mr1 = mn1;

        float s0 = 0.f, s1 = 0.f;
        #pragma unroll
        for (int nt = 0; nt < 4; nt++) {
            sc[nt][0] = ex2f((sc[nt][0] - mn0) * CEXP);
            sc[nt][1] = ex2f((sc[nt][1] - mn0) * CEXP);
            sc[nt][2] = ex2f((sc[nt][2] - mn1) * CEXP);
            sc[nt][3] = ex2f((sc[nt][3] - mn1) * CEXP);
            s0 += sc[nt][0] + sc[nt][1];
            s1 += sc[nt][2] + sc[nt][3];
        }
        s0 += __shfl_xor_sync(0xffffffff, s0, 1);
        s0 += __shfl_xor_sync(0xffffffff, s0, 2);
        s1 += __shfl_xor_sync(0xffffffff, s1, 1);
        s1 += __shfl_xor_sync(0xffffffff, s1, 2);
        lr0 = lr0 * al0 + s0;
        lr1 = lr1 * al1 + s1;

        #pragma unroll
        for (int nt = 0; nt < 16; nt++) {
            oc[nt][0] *= al0; oc[nt][1] *= al0;
            oc[nt][2] *= al1; oc[nt][3] *= al1;
        }

        #pragma unroll
        for (int kc = 0; kc < 2; kc++) {
            uint32_t a0 = pack_h2(sc[2 * kc][0],     sc[2 * kc][1]);
            uint32_t a1 = pack_h2(sc[2 * kc][2],     sc[2 * kc][3]);
            uint32_t a2 = pack_h2(sc[2 * kc + 1][0], sc[2 * kc + 1][1]);
            uint32_t a3 = pack_h2(sc[2 * kc + 1][2], sc[2 * kc + 1][3]);
            #pragma unroll
            for (int ntp = 0; ntp < 8; ntp++) {
                uint4 vb = *(const uint4*)(Vst + (kc * 8 + ntp) * 256 + lane * 8);
                mma_f16(oc[2 * ntp][0], oc[2 * ntp][1], oc[2 * ntp][2], oc[2 * ntp][3],
                        a0, a1, a2, a3, vb.x, vb.y);
                mma_f16(oc[2 * ntp + 1][0], oc[2 * ntp + 1][1],
                        oc[2 * ntp + 1][2], oc[2 * ntp + 1][3],
                        a0, a1, a2, a3, vb.z, vb.w);
            }
        }
    }

    float li0 = 1.f / lr0, li1 = 1.f / lr1;
    __half* orow0 = g_attnh + (size_t)(q0 + wid * 16 + g) * D + h * DH;
    __half* orow1 = orow0 + (size_t)8 * D;
    #pragma unroll
    for (int nt = 0; nt < 16; nt++) {
        *(__half2*)(orow0 + nt * 8 + 2 * t) =
            __float22half2_rn(make_float2(oc[nt][0] * li0, oc[nt][1] * li0));
        *(__half2*)(orow1 + nt * 8 + 2 * t) =
            __float22half2_rn(make_float2(oc[nt][2] * li1, oc[nt][3] * li1));
    }
}

// ---------------- launch ----------------
extern "C" void kernel_launch(void* const* d_in, const int* in_sizes, int n_in,
                              void* d_out, int out_size)
{
    const float* hidden     = (const float*)d_in[0];
    const float* encoder    = (const float*)d_in[1];
    const float* cosb       = (const float*)d_in[2];
    const float* sinb       = (const float*)d_in[3];
    const float* w_qkv      = (const float*)d_in[4];
    const float* w_add_qkv  = (const float*)d_in[5];
    const float* b_add_qkv  = (const float*)d_in[6];
    const float* norm_q_w   = (const float*)d_in[7];
    const float* norm_k_w   = (const float*)d_in[8];
    const float* norm_aq_w  = (const float*)d_in[9];
    const float* norm_ak_w  = (const float*)d_in[10];
    const float* w_out      = (const float*)d_in[11];
    const float* b_out      = (const float*)d_in[12];
    const float* w_add_out  = (const float*)d_in[13];
    const float* b_add_out  = (const float*)d_in[14];
    float* out = (float*)d_out;

    __half *xh, *wqh, *waqh, *woh, *waoh, *attnh;
    cudaGetSymbolAddress((void**)&xh,    g_xh);
    cudaGetSymbolAddress((void**)&wqh,   g_wqkvh);
    cudaGetSymbolAddress((void**)&waqh,  g_waddqkvh);
    cudaGetSymbolAddress((void**)&woh,   g_wouth);
    cudaGetSymbolAddress((void**)&waoh,  g_waddouth);
    cudaGetSymbolAddress((void**)&attnh, g_attnh);

    cudaFuncSetAttribute(flash_f16, cudaFuncAttributeMaxDynamicSharedMemorySize, FLASH_SMEM);
    cudaFuncSetAttribute(gemm_qkv_fused, cudaFuncAttributeMaxDynamicSharedMemorySize, GEMM_SMEM_BYTES);
    cudaFuncSetAttribute(gemm_f16o,      cudaFuncAttributeMaxDynamicSharedMemorySize, GEMM_SMEM_BYTES);

    // 0: conv_all, 1: gemm_qkv_fused, 2: flash, 3: gemm_out (profiled)
    {
        const int NE = TXT * D / 4, NHd = IMG * D / 4;
        const int NW = ND3 * D / 4, NO = D * D / 4;
        const int TOT = NE + NHd + 2 * NW + 2 * NO;
        conv_all<<<(TOT + 255) / 256, 256>>>(
            (const float4*)encoder, (const float4*)hidden,
            (const float4*)w_qkv, (const float4*)w_add_qkv,
            (const float4*)w_out, (const float4*)w_add_out,
            (__half2*)xh, (__half2*)wqh, (__half2*)waqh,
            (__half2*)woh, (__half2*)waoh);
    }

    // QKV projection + fused bias/RMSNorm/RoPE/head-split
    gemm_qkv_fused<<<dim3(S_TOT / BM, ND3 / BN), 128, GEMM_SMEM_BYTES>>>(
        xh, waqh, wqh, b_add_qkv, TXT,
        cosb, sinb, norm_q_w, norm_k_w, norm_aq_w, norm_ak_w);

    // Flash attention (fp16 mma.sync, R10 body)
    flash_f16<<<dim3(S_TOT / QT, NH), 256, FLASH_SMEM>>>();

    // Output projections (fp16 mma.sync, fp32 output)
    gemm_f16o<<<dim3(S_TOT / BM, D / BN), 128, GEMM_SMEM_BYTES>>>(
        attnh, waoh, woh, b_add_out, b_out,
        out + (size_t)IMG * D, out, TXT, D);
}